// round 15
// baseline (speedup 1.0000x reference)
#include <cuda_runtime.h>
#include <cuda_bf16.h>
#include <cstdint>
#include <cstddef>

#define BB 32
#define TT 512
#define DD 512
#define UU 512

// ---------------------------------------------------------------------------
// Device-global scratch (no cudaMalloc allowed)
// ---------------------------------------------------------------------------
__device__ float    g_mx[(size_t)BB * TT * 3 * UU];   // x@kernel + bias
__device__ float    g_rh[BB * UU];                    // r*h exchange buffer
__device__ unsigned g_cnt[8];                         // cumulative arrivals
__device__ unsigned g_ep[8];                          // published epoch

__device__ __forceinline__ float hsig(float x) {
    return fminf(fmaxf(fmaf(0.2f, x, 0.5f), 0.0f), 1.0f);
}

// ---------------------------------------------------------------------------
// Kernel 1: mx = x @ kernel + bias   (M=16384, N=1536, K=512) — FFMA roofline
// ---------------------------------------------------------------------------
__global__ __launch_bounds__(256) void mx_gemm(const float* __restrict__ X,
                                               const float* __restrict__ W,
                                               const float* __restrict__ bias) {
    __shared__ float As[16][132];
    __shared__ float Bs[16][68];

    const int tid = threadIdx.x;
    const int m0  = blockIdx.y * 128;
    const int n0  = blockIdx.x * 64;
    const int tm  = tid & 15;
    const int tn  = tid >> 4;

    float acc[8][4];
#pragma unroll
    for (int i = 0; i < 8; i++)
#pragma unroll
        for (int j = 0; j < 4; j++) acc[i][j] = 0.0f;

    for (int kk = 0; kk < DD; kk += 16) {
#pragma unroll
        for (int jj = 0; jj < 2; jj++) {
            int idx = tid + jj * 256;
            int r   = idx >> 2;
            int kq  = (idx & 3) << 2;
            float4 v = *(const float4*)&X[(size_t)(m0 + r) * DD + kk + kq];
            As[kq + 0][r] = v.x;
            As[kq + 1][r] = v.y;
            As[kq + 2][r] = v.z;
            As[kq + 3][r] = v.w;
        }
        {
            int kr = tid >> 4;
            int nq = (tid & 15) << 2;
            float4 v = *(const float4*)&W[(size_t)(kk + kr) * (3 * UU) + n0 + nq];
            *(float4*)&Bs[kr][nq] = v;
        }
        __syncthreads();

#pragma unroll
        for (int k = 0; k < 16; k++) {
            float4 a0 = *(const float4*)&As[k][tm << 2];
            float4 a1 = *(const float4*)&As[k][64 + (tm << 2)];
            float4 b0 = *(const float4*)&Bs[k][tn << 2];
            float af[8] = {a0.x, a0.y, a0.z, a0.w, a1.x, a1.y, a1.z, a1.w};
            float bf[4] = {b0.x, b0.y, b0.z, b0.w};
#pragma unroll
            for (int i = 0; i < 8; i++)
#pragma unroll
                for (int j = 0; j < 4; j++) acc[i][j] = fmaf(af[i], bf[j], acc[i][j]);
        }
        __syncthreads();
    }

    float4 bv = *(const float4*)&bias[n0 + (tn << 2)];
#pragma unroll
    for (int i = 0; i < 8; i++) {
        int m = (i < 4) ? ((tm << 2) + i) : (64 + (tm << 2) + (i - 4));
        float4 o;
        o.x = acc[i][0] + bv.x;
        o.y = acc[i][1] + bv.y;
        o.z = acc[i][2] + bv.z;
        o.w = acc[i][3] + bv.w;
        *(float4*)&g_mx[(size_t)(m0 + m) * (3 * UU) + n0 + (tn << 2)] = o;
    }
}

#define RED2(v) do { \
    (v) += __shfl_xor_sync(0xffffffffu, (v), 8);  \
    (v) += __shfl_xor_sync(0xffffffffu, (v), 16); \
} while (0)

// Register-weight pass: stage[4][512] @ W(8u x 4c regs) -> red
#define PASS_REG(WREG, STAGE, RED) do {                                        \
    float a[4][4];                                                             \
    _Pragma("unroll")                                                          \
    for (int b = 0; b < 4; b++)                                                \
        _Pragma("unroll")                                                      \
        for (int c = 0; c < 4; c++) a[b][c] = 0.0f;                            \
    _Pragma("unroll")                                                          \
    for (int uu = 0; uu < 8; uu++) {                                           \
        int u = ub + uu;                                                       \
        float4 wv = WREG[uu];                                                  \
        float h0 = (STAGE)[u], h1 = (STAGE)[512 + u];                          \
        float h2 = (STAGE)[1024 + u], h3 = (STAGE)[1536 + u];                  \
        a[0][0] = fmaf(h0, wv.x, a[0][0]); a[0][1] = fmaf(h0, wv.y, a[0][1]);  \
        a[0][2] = fmaf(h0, wv.z, a[0][2]); a[0][3] = fmaf(h0, wv.w, a[0][3]);  \
        a[1][0] = fmaf(h1, wv.x, a[1][0]); a[1][1] = fmaf(h1, wv.y, a[1][1]);  \
        a[1][2] = fmaf(h1, wv.z, a[1][2]); a[1][3] = fmaf(h1, wv.w, a[1][3]);  \
        a[2][0] = fmaf(h2, wv.x, a[2][0]); a[2][1] = fmaf(h2, wv.y, a[2][1]);  \
        a[2][2] = fmaf(h2, wv.z, a[2][2]); a[2][3] = fmaf(h2, wv.w, a[2][3]);  \
        a[3][0] = fmaf(h3, wv.x, a[3][0]); a[3][1] = fmaf(h3, wv.y, a[3][1]);  \
        a[3][2] = fmaf(h3, wv.z, a[3][2]); a[3][3] = fmaf(h3, wv.w, a[3][3]);  \
    }                                                                          \
    _Pragma("unroll")                                                          \
    for (int b = 0; b < 4; b++)                                                \
        _Pragma("unroll")                                                      \
        for (int c = 0; c < 4; c++) RED2(a[b][c]);                             \
    if (l < 8)                                                                 \
        _Pragma("unroll")                                                      \
        for (int b = 0; b < 4; b++)                                            \
            *(float4*)&(RED)[(w << 7) + (b << 5) + (l << 2)] =                 \
                make_float4(a[b][0], a[b][1], a[b][2], a[b][3]);               \
} while (0)

// SMEM-weight pass (Wh)
#define PASS_WH(STAGE, RED) do {                                               \
    float a[4][4];                                                             \
    _Pragma("unroll")                                                          \
    for (int b = 0; b < 4; b++)                                                \
        _Pragma("unroll")                                                      \
        for (int c = 0; c < 4; c++) a[b][c] = 0.0f;                            \
    _Pragma("unroll")                                                          \
    for (int uu = 0; uu < 8; uu++) {                                           \
        int u = ub + uu;                                                       \
        float4 wv = *(const float4*)&s->wh[(u << 5) + (cs << 2)];              \
        float h0 = (STAGE)[u], h1 = (STAGE)[512 + u];                          \
        float h2 = (STAGE)[1024 + u], h3 = (STAGE)[1536 + u];                  \
        a[0][0] = fmaf(h0, wv.x, a[0][0]); a[0][1] = fmaf(h0, wv.y, a[0][1]);  \
        a[0][2] = fmaf(h0, wv.z, a[0][2]); a[0][3] = fmaf(h0, wv.w, a[0][3]);  \
        a[1][0] = fmaf(h1, wv.x, a[1][0]); a[1][1] = fmaf(h1, wv.y, a[1][1]);  \
        a[1][2] = fmaf(h1, wv.z, a[1][2]); a[1][3] = fmaf(h1, wv.w, a[1][3]);  \
        a[2][0] = fmaf(h2, wv.x, a[2][0]); a[2][1] = fmaf(h2, wv.y, a[2][1]);  \
        a[2][2] = fmaf(h2, wv.z, a[2][2]); a[2][3] = fmaf(h2, wv.w, a[2][3]);  \
        a[3][0] = fmaf(h3, wv.x, a[3][0]); a[3][1] = fmaf(h3, wv.y, a[3][1]);  \
        a[3][2] = fmaf(h3, wv.z, a[3][2]); a[3][3] = fmaf(h3, wv.w, a[3][3]);  \
    }                                                                          \
    _Pragma("unroll")                                                          \
    for (int b = 0; b < 4; b++)                                                \
        _Pragma("unroll")                                                      \
        for (int c = 0; c < 4; c++) RED2(a[b][c]);                             \
    if (l < 8)                                                                 \
        _Pragma("unroll")                                                      \
        for (int b = 0; b < 4; b++)                                            \
            *(float4*)&(RED)[(w << 7) + (b << 5) + (l << 2)] =                 \
                make_float4(a[b][0], a[b][1], a[b][2], a[b][3]);               \
} while (0)

// ===========================================================================
// Dual-group GRU: 64 CTAs = 4 superblocks x 16 col-CTAs. Each CTA serves the
// SAME 32 columns of TWO batch-groups (A, B), interleaved so each group's
// barrier latency hides under the other group's compute. 512 thr, 1 CTA/SM.
// ===========================================================================
struct SMD {
    float wh[512 * 32];        // 64 KB (shared by both groups)
    float stage[2][4 * 512];   // 16 KB
    float red[2][2048];        // 16 KB
    float zs[2][128];
    float hown[2][128];
};
#define SMD_BYTES ((int)sizeof(SMD))

__global__ __launch_bounds__(512, 1) void gru_dual(const float* __restrict__ RK,
                                                   float* __restrict__ out) {
    extern __shared__ char raw[];
    SMD* s = (SMD*)raw;
    __shared__ unsigned e0[2];

    const int tid = threadIdx.x;
    const int sb  = blockIdx.x >> 4;      // 0..3 superblock
    const int cid = blockIdx.x & 15;      // 0..15
    const int j0  = cid << 5;
    const int grpG[2] = { sb << 1, (sb << 1) | 1 };
    const int gb0G[2] = { grpG[0] << 2, grpG[1] << 2 };

    const int ks = tid >> 3;
    const int cs = tid & 7;
    const int ub = ks << 3;
    const int w  = tid >> 5;
    const int l  = tid & 31;
    const int gate = tid >> 7;            // tid<256: 0=z, 1=r
    const int rb   = (tid >> 5) & 3;
    const int rc   = tid & 31;

    // weights: Wh -> SMEM, Wz/Wr -> registers (shared across groups)
    for (int i = tid; i < (512 * 32) / 4; i += 512) {
        int f = i << 2;
        int u = f >> 5, c = f & 31;
        *(float4*)&s->wh[f] = *(const float4*)&RK[(size_t)u * 1536 + 1024 + j0 + c];
    }
    float4 wz[8], wr[8];
#pragma unroll
    for (int uu = 0; uu < 8; uu++) {
        const float* bp = &RK[(size_t)(ub + uu) * 1536 + j0 + (cs << 2)];
        wz[uu] = *(const float4*)bp;
        wr[uu] = *(const float4*)(bp + 512);
    }

    if (tid == 0) {
        e0[0] = *(volatile unsigned*)&g_ep[grpG[0]];
        e0[1] = *(volatile unsigned*)&g_ep[grpG[1]];
    }
    __syncthreads();
    unsigned tgt[2] = { e0[0], e0[1] };

    auto ARRIVE = [&](int g) {
        __threadfence();
        __syncthreads();
        if (tid == 0) {
            unsigned p = atomicAdd(&g_cnt[grpG[g]], 1u);
            if (((p + 1u) & 15u) == 0u) {
                __threadfence();
                *(volatile unsigned*)&g_ep[grpG[g]] = (p + 1u) >> 4;
            }
        }
    };
    auto WAIT = [&](int g) {
        if (tid == 0) {
            while ((int)(*(volatile unsigned*)&g_ep[grpG[g]] - tgt[g]) < 0)
                __nanosleep(32);
        }
        __syncthreads();
    };

    // ---- t = 0 for both groups ----
    if (tid < 128) {
#pragma unroll
        for (int g = 0; g < 2; g++) {
            size_t mrow = (size_t)(gb0G[g] + rb) * TT * 1536;
            float z  = hsig(g_mx[mrow + j0 + rc]);
            float hh = tanhf(g_mx[mrow + 1024 + j0 + rc]);
            out[(size_t)(gb0G[g] + rb) * TT * UU + j0 + rc] = (1.0f - z) * hh;
        }
    }
    ARRIVE(0); ++tgt[0];
    ARRIVE(1); ++tgt[1];

#pragma unroll 1
    for (int t = 1; t < TT; t++) {
        // prefetch mx gate terms for both groups
        float pm1[2] = {0.0f, 0.0f}, pm2[2] = {0.0f, 0.0f};
#pragma unroll
        for (int g = 0; g < 2; g++) {
            if (tid < 256) {
                size_t mrow = ((size_t)(gb0G[g] + rb) * TT + t) * 1536;
                pm1[g] = __ldcg(&g_mx[mrow + (gate << 9) + j0 + rc]);
                if (tid < 128) pm2[g] = __ldcg(&g_mx[mrow + 1024 + j0 + rc]);
            }
        }

        // ======== H1(A), H1(B): wait h, stage, r-pass, publish rh ========
#pragma unroll
        for (int g = 0; g < 2; g++) {
            WAIT(g);
            {
                int b = tid >> 7, ug = tid & 127;
                float4 v = __ldcg((const float4*)(
                    out + ((size_t)(gb0G[g] + b) * TT + (t - 1)) * UU) + ug);
                *(float4*)&s->stage[g][(b << 9) + (ug << 2)] = v;
            }
            __syncthreads();
            PASS_REG(wr, s->stage[g], s->red[g]);
            __syncthreads();
            if (gate == 1 && tid < 256) {
                int idx = tid - 128;
                float sum = pm1[g];
#pragma unroll
                for (int k = 0; k < 16; k++) sum += s->red[g][(k << 7) + idx];
                float r = hsig(sum);
                g_rh[(size_t)(gb0G[g] + rb) * UU + j0 + rc] =
                    r * s->stage[g][(rb << 9) + j0 + rc];
            }
            ARRIVE(g); ++tgt[g];
        }

        // ======== H2(A), H2(B): z-pass, wait rh, stage, h-pass, final ====
#pragma unroll
        for (int g = 0; g < 2; g++) {
            PASS_REG(wz, s->stage[g], s->red[g]);
            __syncthreads();
            if (gate == 0 && tid < 128) {
                float sum = pm1[g];
#pragma unroll
                for (int k = 0; k < 16; k++) sum += s->red[g][(k << 7) + tid];
                s->zs[g][tid]   = hsig(sum);
                s->hown[g][tid] = s->stage[g][(rb << 9) + j0 + rc];
            }
            WAIT(g);
            {
                int b = tid >> 7, ug = tid & 127;
                float4 v = __ldcg((const float4*)(
                    g_rh + (size_t)(gb0G[g] + b) * UU) + ug);
                *(float4*)&s->stage[g][(b << 9) + (ug << 2)] = v;
            }
            __syncthreads();
            PASS_WH(s->stage[g], s->red[g]);
            __syncthreads();
            if (tid < 128) {
                float sum = pm2[g];
#pragma unroll
                for (int k = 0; k < 16; k++) sum += s->red[g][(k << 7) + tid];
                float hh = tanhf(sum);
                float z  = s->zs[g][tid];
                float hp = s->hown[g][tid];
                out[((size_t)(gb0G[g] + rb) * TT + t) * UU + j0 + rc] =
                    z * hp + (1.0f - z) * hh;
            }
            ARRIVE(g); ++tgt[g];
        }
    }
}

// ---------------------------------------------------------------------------
extern "C" void kernel_launch(void* const* d_in, const int* in_sizes, int n_in,
                              void* d_out, int out_size) {
    const float* x    = (const float*)d_in[0];
    const float* ker  = (const float*)d_in[1];
    const float* rk   = (const float*)d_in[2];
    const float* bias = (const float*)d_in[3];
    float* out = (float*)d_out;
    (void)in_sizes; (void)n_in; (void)out_size;

    static bool attr_set = false;
    if (!attr_set) {
        cudaFuncSetAttribute(gru_dual, cudaFuncAttributeMaxDynamicSharedMemorySize,
                             SMD_BYTES);
        attr_set = true;
    }

    dim3 gg(24, 128);
    mx_gemm<<<gg, 256>>>(x, ker, bias);
    gru_dual<<<64, 512, SMD_BYTES>>>(rk, out);
}

// round 16
// speedup vs baseline: 2.0631x; 2.0631x over previous
#include <cuda_runtime.h>
#include <cuda_bf16.h>
#include <cstdint>
#include <cstddef>

#define BB 32
#define TT 512
#define DD 512
#define UU 512

// ---------------------------------------------------------------------------
// Device-global scratch (no cudaMalloc allowed)
// ---------------------------------------------------------------------------
__device__ float    g_mx[(size_t)BB * TT * 3 * UU];   // x@kernel + bias
__device__ float    g_rh[BB * UU];                    // r*h exchange (hot)
__device__ float    g_h[2][BB][UU];                   // h exchange (hot, 2-buf)
__device__ unsigned g_cnt[8];                         // cumulative arrivals

__device__ __forceinline__ float hsig(float x) {
    return fminf(fmaxf(fmaf(0.2f, x, 0.5f), 0.0f), 1.0f);
}

// ---------------------------------------------------------------------------
// Kernel 1: mx = x @ kernel + bias   (M=16384, N=1536, K=512) — FFMA roofline
// ---------------------------------------------------------------------------
__global__ __launch_bounds__(256) void mx_gemm(const float* __restrict__ X,
                                               const float* __restrict__ W,
                                               const float* __restrict__ bias) {
    __shared__ float As[16][132];
    __shared__ float Bs[16][68];

    const int tid = threadIdx.x;
    const int m0  = blockIdx.y * 128;
    const int n0  = blockIdx.x * 64;
    const int tm  = tid & 15;
    const int tn  = tid >> 4;

    float acc[8][4];
#pragma unroll
    for (int i = 0; i < 8; i++)
#pragma unroll
        for (int j = 0; j < 4; j++) acc[i][j] = 0.0f;

    for (int kk = 0; kk < DD; kk += 16) {
#pragma unroll
        for (int jj = 0; jj < 2; jj++) {
            int idx = tid + jj * 256;
            int r   = idx >> 2;
            int kq  = (idx & 3) << 2;
            float4 v = *(const float4*)&X[(size_t)(m0 + r) * DD + kk + kq];
            As[kq + 0][r] = v.x;
            As[kq + 1][r] = v.y;
            As[kq + 2][r] = v.z;
            As[kq + 3][r] = v.w;
        }
        {
            int kr = tid >> 4;
            int nq = (tid & 15) << 2;
            float4 v = *(const float4*)&W[(size_t)(kk + kr) * (3 * UU) + n0 + nq];
            *(float4*)&Bs[kr][nq] = v;
        }
        __syncthreads();

#pragma unroll
        for (int k = 0; k < 16; k++) {
            float4 a0 = *(const float4*)&As[k][tm << 2];
            float4 a1 = *(const float4*)&As[k][64 + (tm << 2)];
            float4 b0 = *(const float4*)&Bs[k][tn << 2];
            float af[8] = {a0.x, a0.y, a0.z, a0.w, a1.x, a1.y, a1.z, a1.w};
            float bf[4] = {b0.x, b0.y, b0.z, b0.w};
#pragma unroll
            for (int i = 0; i < 8; i++)
#pragma unroll
                for (int j = 0; j < 4; j++) acc[i][j] = fmaf(af[i], bf[j], acc[i][j]);
        }
        __syncthreads();
    }

    float4 bv = *(const float4*)&bias[n0 + (tn << 2)];
#pragma unroll
    for (int i = 0; i < 8; i++) {
        int m = (i < 4) ? ((tm << 2) + i) : (64 + (tm << 2) + (i - 4));
        float4 o;
        o.x = acc[i][0] + bv.x;
        o.y = acc[i][1] + bv.y;
        o.z = acc[i][2] + bv.z;
        o.w = acc[i][3] + bv.w;
        *(float4*)&g_mx[(size_t)(m0 + m) * (3 * UU) + n0 + (tn << 2)] = o;
    }
}

#define RED2(v) do { \
    (v) += __shfl_xor_sync(0xffffffffu, (v), 8);  \
    (v) += __shfl_xor_sync(0xffffffffu, (v), 16); \
} while (0)

// ===========================================================================
// GRU recurrence (R10 structure): 128 CTAs = 8 groups (x4 batches) * 16
// col-CTAs (x32 cols), 512 threads, 1 CTA/SM. Deltas vs R10:
//   - h exchanged via compact hot g_h[2] double buffer (not via `out`)
//   - `out` written after ARRIVE (off critical path / out of fence set)
//   - waiters poll g_cnt directly (no epoch store round trip)
// ===========================================================================
struct SM16 {
    float wh[512 * 32];     // 64 KB
    float stage[4][512];    // 8 KB (h, then rh)
    float red[16 * 128];    // 8 KB
    float zs[128], hown[128];
    unsigned c0;
};
#define SM16_BYTES ((int)sizeof(SM16))

__global__ __launch_bounds__(512, 1) void gru16(const float* __restrict__ RK,
                                                float* __restrict__ out) {
    extern __shared__ char raw[];
    SM16* s = (SM16*)raw;
    const int tid = threadIdx.x;
    const int grp = blockIdx.x >> 4;          // 0..7
    const int gb0 = grp << 2;
    const int j0  = (blockIdx.x & 15) << 5;   // 32 unit cols

    const int ks = tid >> 3;                  // 0..63, u = ks*8 .. +7
    const int cs = tid & 7;                   // cols cs*4 .. +3
    const int ub = ks << 3;
    const int w  = tid >> 5;
    const int l  = tid & 31;

    const int gate = tid >> 7;                // tid<256: 0=z, 1=r
    const int rb   = (tid >> 5) & 3;
    const int rc   = tid & 31;

    // ---- weights: Wh -> SMEM, Wz/Wr -> registers ----
    for (int i = tid; i < (512 * 32) / 4; i += 512) {
        int f = i << 2;
        int u = f >> 5, c = f & 31;
        *(float4*)&s->wh[f] = *(const float4*)&RK[(size_t)u * 1536 + 1024 + j0 + c];
    }
    float4 wz[8], wr[8];
#pragma unroll
    for (int uu = 0; uu < 8; uu++) {
        const float* bp = &RK[(size_t)(ub + uu) * 1536 + j0 + (cs << 2)];
        wz[uu] = *(const float4*)bp;
        wr[uu] = *(const float4*)(bp + 512);
    }

    if (tid == 0) s->c0 = *(volatile unsigned*)&g_cnt[grp];
    __syncthreads();
    unsigned tcnt = s->c0;                    // absolute count target base

    auto ARRIVE = [&]() {
        __threadfence();
        __syncthreads();
        if (tid == 0) atomicAdd(&g_cnt[grp], 1u);
    };
    auto WAIT = [&](unsigned target) {        // target = absolute count
        if (tid == 0) {
            while ((int)(*(volatile unsigned*)&g_cnt[grp] - target) < 0) {
                __nanosleep(32);
            }
        }
        __syncthreads();
    };

    // ---- t = 0 : h_prev = 0 ----
    float h0v = 0.0f;
    if (tid < 128) {
        size_t mrow = (size_t)(gb0 + rb) * TT * 1536;
        float z  = hsig(g_mx[mrow + j0 + rc]);
        float hh = tanhf(g_mx[mrow + 1024 + j0 + rc]);
        h0v = (1.0f - z) * hh;
        g_h[0][gb0 + rb][j0 + rc] = h0v;
    }
    ARRIVE(); tcnt += 16;
    if (tid < 128)
        out[(size_t)(gb0 + rb) * TT * UU + j0 + rc] = h0v;

#pragma unroll 1
    for (int t = 1; t < TT; t++) {
        const int bh = (t - 1) & 1;           // h buffer to read
        const int bw = t & 1;                 // h buffer to write

        // prefetch mx gate terms (independent of sync)
        float pm1 = 0.0f, pm2 = 0.0f;
        if (tid < 256) {
            size_t mrow = ((size_t)(gb0 + rb) * TT + t) * 1536;
            pm1 = __ldcg(&g_mx[mrow + (gate << 9) + j0 + rc]);
            if (tid < 128) pm2 = __ldcg(&g_mx[mrow + 1024 + j0 + rc]);
        }

        // ---- wait h(t-1) ----
        WAIT(tcnt);

        // ---- stage h(t-1) from hot buffer ----
        {
            int b = tid >> 7, ug = tid & 127;
            float4 v = __ldcg((const float4*)&g_h[bh][gb0 + b][0] + ug);
            *(float4*)&s->stage[b][ug << 2] = v;
        }
        __syncthreads();

        // ---- r pass (critical path) ----
        {
            float a[4][4];
#pragma unroll
            for (int b = 0; b < 4; b++)
#pragma unroll
                for (int c = 0; c < 4; c++) a[b][c] = 0.0f;
#pragma unroll
            for (int uu = 0; uu < 8; uu++) {
                int u = ub + uu;
                float4 wv = wr[uu];
                float h0 = s->stage[0][u], h1 = s->stage[1][u];
                float h2 = s->stage[2][u], h3 = s->stage[3][u];
                a[0][0] = fmaf(h0, wv.x, a[0][0]); a[0][1] = fmaf(h0, wv.y, a[0][1]);
                a[0][2] = fmaf(h0, wv.z, a[0][2]); a[0][3] = fmaf(h0, wv.w, a[0][3]);
                a[1][0] = fmaf(h1, wv.x, a[1][0]); a[1][1] = fmaf(h1, wv.y, a[1][1]);
                a[1][2] = fmaf(h1, wv.z, a[1][2]); a[1][3] = fmaf(h1, wv.w, a[1][3]);
                a[2][0] = fmaf(h2, wv.x, a[2][0]); a[2][1] = fmaf(h2, wv.y, a[2][1]);
                a[2][2] = fmaf(h2, wv.z, a[2][2]); a[2][3] = fmaf(h2, wv.w, a[2][3]);
                a[3][0] = fmaf(h3, wv.x, a[3][0]); a[3][1] = fmaf(h3, wv.y, a[3][1]);
                a[3][2] = fmaf(h3, wv.z, a[3][2]); a[3][3] = fmaf(h3, wv.w, a[3][3]);
            }
#pragma unroll
            for (int b = 0; b < 4; b++)
#pragma unroll
                for (int c = 0; c < 4; c++) RED2(a[b][c]);
            if (l < 8)
#pragma unroll
                for (int b = 0; b < 4; b++)
                    *(float4*)&s->red[(w << 7) + (b << 5) + (l << 2)] =
                        make_float4(a[b][0], a[b][1], a[b][2], a[b][3]);
        }
        __syncthreads();

        // ---- r reduce -> publish rh (threads 128..255 hold pm1 = mx_r) ----
        if (gate == 1 && tid < 256) {
            int idx = tid - 128;
            float sum = pm1;
#pragma unroll
            for (int k = 0; k < 16; k++) sum += s->red[(k << 7) + idx];
            float r = hsig(sum);
            g_rh[(size_t)(gb0 + rb) * UU + j0 + rc] = r * s->stage[rb][j0 + rc];
        }
        ARRIVE(); tcnt += 16;     // rh published  (no wait yet)

        // ======== hidden work: z pass while peers publish rh ========
        {
            float a[4][4];
#pragma unroll
            for (int b = 0; b < 4; b++)
#pragma unroll
                for (int c = 0; c < 4; c++) a[b][c] = 0.0f;
#pragma unroll
            for (int uu = 0; uu < 8; uu++) {
                int u = ub + uu;
                float4 wv = wz[uu];
                float h0 = s->stage[0][u], h1 = s->stage[1][u];
                float h2 = s->stage[2][u], h3 = s->stage[3][u];
                a[0][0] = fmaf(h0, wv.x, a[0][0]); a[0][1] = fmaf(h0, wv.y, a[0][1]);
                a[0][2] = fmaf(h0, wv.z, a[0][2]); a[0][3] = fmaf(h0, wv.w, a[0][3]);
                a[1][0] = fmaf(h1, wv.x, a[1][0]); a[1][1] = fmaf(h1, wv.y, a[1][1]);
                a[1][2] = fmaf(h1, wv.z, a[1][2]); a[1][3] = fmaf(h1, wv.w, a[1][3]);
                a[2][0] = fmaf(h2, wv.x, a[2][0]); a[2][1] = fmaf(h2, wv.y, a[2][1]);
                a[2][2] = fmaf(h2, wv.z, a[2][2]); a[2][3] = fmaf(h2, wv.w, a[2][3]);
                a[3][0] = fmaf(h3, wv.x, a[3][0]); a[3][1] = fmaf(h3, wv.y, a[3][1]);
                a[3][2] = fmaf(h3, wv.z, a[3][2]); a[3][3] = fmaf(h3, wv.w, a[3][3]);
            }
#pragma unroll
            for (int b = 0; b < 4; b++)
#pragma unroll
                for (int c = 0; c < 4; c++) RED2(a[b][c]);
            if (l < 8)
#pragma unroll
                for (int b = 0; b < 4; b++)
                    *(float4*)&s->red[(w << 7) + (b << 5) + (l << 2)] =
                        make_float4(a[b][0], a[b][1], a[b][2], a[b][3]);
        }
        __syncthreads();
        if (gate == 0 && tid < 128) {     // threads 0..127 hold pm1 = mx_z
            float sum = pm1;
#pragma unroll
            for (int k = 0; k < 16; k++) sum += s->red[(k << 7) + tid];
            s->zs[tid]   = hsig(sum);
            s->hown[tid] = s->stage[rb][j0 + rc];
        }
        // ============================================================

        // ---- wait rh from all group CTAs, stage it ----
        WAIT(tcnt);
        {
            int b = tid >> 7, ug = tid & 127;
            float4 v = __ldcg((const float4*)(g_rh + (size_t)(gb0 + b) * UU) + ug);
            *(float4*)&s->stage[b][ug << 2] = v;
        }
        __syncthreads();

        // ---- h-candidate pass (Wh from SMEM) ----
        {
            float a[4][4];
#pragma unroll
            for (int b = 0; b < 4; b++)
#pragma unroll
                for (int c = 0; c < 4; c++) a[b][c] = 0.0f;
#pragma unroll
            for (int uu = 0; uu < 8; uu++) {
                int u = ub + uu;
                float4 wv = *(const float4*)&s->wh[(u << 5) + (cs << 2)];
                float h0 = s->stage[0][u], h1 = s->stage[1][u];
                float h2 = s->stage[2][u], h3 = s->stage[3][u];
                a[0][0] = fmaf(h0, wv.x, a[0][0]); a[0][1] = fmaf(h0, wv.y, a[0][1]);
                a[0][2] = fmaf(h0, wv.z, a[0][2]); a[0][3] = fmaf(h0, wv.w, a[0][3]);
                a[1][0] = fmaf(h1, wv.x, a[1][0]); a[1][1] = fmaf(h1, wv.y, a[1][1]);
                a[1][2] = fmaf(h1, wv.z, a[1][2]); a[1][3] = fmaf(h1, wv.w, a[1][3]);
                a[2][0] = fmaf(h2, wv.x, a[2][0]); a[2][1] = fmaf(h2, wv.y, a[2][1]);
                a[2][2] = fmaf(h2, wv.z, a[2][2]); a[2][3] = fmaf(h2, wv.w, a[2][3]);
                a[3][0] = fmaf(h3, wv.x, a[3][0]); a[3][1] = fmaf(h3, wv.y, a[3][1]);
                a[3][2] = fmaf(h3, wv.z, a[3][2]); a[3][3] = fmaf(h3, wv.w, a[3][3]);
            }
#pragma unroll
            for (int b = 0; b < 4; b++)
#pragma unroll
                for (int c = 0; c < 4; c++) RED2(a[b][c]);
            if (l < 8)
#pragma unroll
                for (int b = 0; b < 4; b++)
                    *(float4*)&s->red[(w << 7) + (b << 5) + (l << 2)] =
                        make_float4(a[b][0], a[b][1], a[b][2], a[b][3]);
        }
        __syncthreads();

        // ---- final: h(t) -> hot buffer, then publish ----
        float hn = 0.0f;
        if (tid < 128) {
            float sum = pm2;
#pragma unroll
            for (int k = 0; k < 16; k++) sum += s->red[(k << 7) + tid];
            float hh = tanhf(sum);
            float z  = s->zs[tid];
            float hp = s->hown[tid];
            hn = z * hp + (1.0f - z) * hh;
            g_h[bw][gb0 + rb][j0 + rc] = hn;
        }
        ARRIVE(); tcnt += 16;     // h(t) published; wait at next loop top

        // lazy output write (off critical path, outside fence set)
        if (tid < 128)
            out[((size_t)(gb0 + rb) * TT + t) * UU + j0 + rc] = hn;
    }
}

// ---------------------------------------------------------------------------
extern "C" void kernel_launch(void* const* d_in, const int* in_sizes, int n_in,
                              void* d_out, int out_size) {
    const float* x    = (const float*)d_in[0];
    const float* ker  = (const float*)d_in[1];
    const float* rk   = (const float*)d_in[2];
    const float* bias = (const float*)d_in[3];
    float* out = (float*)d_out;
    (void)in_sizes; (void)n_in; (void)out_size;

    static bool attr_set = false;
    if (!attr_set) {
        cudaFuncSetAttribute(gru16, cudaFuncAttributeMaxDynamicSharedMemorySize,
                             SM16_BYTES);
        attr_set = true;
    }

    dim3 gg(24, 128);
    mx_gemm<<<gg, 256>>>(x, ker, bias);
    gru16<<<128, 512, SM16_BYTES>>>(rk, out);
}

// round 17
// speedup vs baseline: 2.3607x; 1.1443x over previous
#include <cuda_runtime.h>
#include <cuda_bf16.h>
#include <cstdint>
#include <cstddef>

#define BB 32
#define TT 512
#define DD 512
#define UU 512

// ---------------------------------------------------------------------------
// Device-global scratch (no cudaMalloc allowed)
// ---------------------------------------------------------------------------
__device__ float    g_mx[(size_t)BB * TT * 3 * UU];   // x@kernel + bias
__device__ float    g_rh[BB * UU];                    // r*h exchange (hot)
__device__ float    g_h[2][BB][UU];                   // h exchange (hot, 2-buf)
__device__ unsigned g_cnt[8];                         // cumulative arrivals

__device__ __forceinline__ float hsig(float x) {
    return fminf(fmaxf(fmaf(0.2f, x, 0.5f), 0.0f), 1.0f);
}

// ---------------------------------------------------------------------------
// Kernel 1: mx = x @ kernel + bias   (M=16384, N=1536, K=512) — FFMA roofline
// ---------------------------------------------------------------------------
__global__ __launch_bounds__(256) void mx_gemm(const float* __restrict__ X,
                                               const float* __restrict__ W,
                                               const float* __restrict__ bias) {
    __shared__ float As[16][132];
    __shared__ float Bs[16][68];

    const int tid = threadIdx.x;
    const int m0  = blockIdx.y * 128;
    const int n0  = blockIdx.x * 64;
    const int tm  = tid & 15;
    const int tn  = tid >> 4;

    float acc[8][4];
#pragma unroll
    for (int i = 0; i < 8; i++)
#pragma unroll
        for (int j = 0; j < 4; j++) acc[i][j] = 0.0f;

    for (int kk = 0; kk < DD; kk += 16) {
#pragma unroll
        for (int jj = 0; jj < 2; jj++) {
            int idx = tid + jj * 256;
            int r   = idx >> 2;
            int kq  = (idx & 3) << 2;
            float4 v = *(const float4*)&X[(size_t)(m0 + r) * DD + kk + kq];
            As[kq + 0][r] = v.x;
            As[kq + 1][r] = v.y;
            As[kq + 2][r] = v.z;
            As[kq + 3][r] = v.w;
        }
        {
            int kr = tid >> 4;
            int nq = (tid & 15) << 2;
            float4 v = *(const float4*)&W[(size_t)(kk + kr) * (3 * UU) + n0 + nq];
            *(float4*)&Bs[kr][nq] = v;
        }
        __syncthreads();

#pragma unroll
        for (int k = 0; k < 16; k++) {
            float4 a0 = *(const float4*)&As[k][tm << 2];
            float4 a1 = *(const float4*)&As[k][64 + (tm << 2)];
            float4 b0 = *(const float4*)&Bs[k][tn << 2];
            float af[8] = {a0.x, a0.y, a0.z, a0.w, a1.x, a1.y, a1.z, a1.w};
            float bf[4] = {b0.x, b0.y, b0.z, b0.w};
#pragma unroll
            for (int i = 0; i < 8; i++)
#pragma unroll
                for (int j = 0; j < 4; j++) acc[i][j] = fmaf(af[i], bf[j], acc[i][j]);
        }
        __syncthreads();
    }

    float4 bv = *(const float4*)&bias[n0 + (tn << 2)];
#pragma unroll
    for (int i = 0; i < 8; i++) {
        int m = (i < 4) ? ((tm << 2) + i) : (64 + (tm << 2) + (i - 4));
        float4 o;
        o.x = acc[i][0] + bv.x;
        o.y = acc[i][1] + bv.y;
        o.z = acc[i][2] + bv.z;
        o.w = acc[i][3] + bv.w;
        *(float4*)&g_mx[(size_t)(m0 + m) * (3 * UU) + n0 + (tn << 2)] = o;
    }
}

#define RED2(v) do { \
    (v) += __shfl_xor_sync(0xffffffffu, (v), 8);  \
    (v) += __shfl_xor_sync(0xffffffffu, (v), 16); \
} while (0)

// ===========================================================================
// GRU recurrence (R16 structure): 128 CTAs = 8 groups (x4 batches) * 16
// col-CTAs (x32 cols), 512 threads, 1 CTA/SM. Delta vs R16:
//   - ARRIVE: __syncthreads first, fence+atomic on tid0 ONLY (non-leader
//     threads enter the z-window / prefetch without paying the gpu-scope
//     drain). Correct per PTX causality (bar.sync synchronizes, tid0's
//     fence covers everything that happens-before it).
//   - WAIT: fast-path first poll (no initial nanosleep).
// ===========================================================================
struct SM16 {
    float wh[512 * 32];     // 64 KB
    float stage[4][512];    // 8 KB (h, then rh)
    float red[16 * 128];    // 8 KB
    float zs[128], hown[128];
    unsigned c0;
};
#define SM16_BYTES ((int)sizeof(SM16))

__global__ __launch_bounds__(512, 1) void gru16(const float* __restrict__ RK,
                                                float* __restrict__ out) {
    extern __shared__ char raw[];
    SM16* s = (SM16*)raw;
    const int tid = threadIdx.x;
    const int grp = blockIdx.x >> 4;          // 0..7
    const int gb0 = grp << 2;
    const int j0  = (blockIdx.x & 15) << 5;   // 32 unit cols

    const int ks = tid >> 3;                  // 0..63, u = ks*8 .. +7
    const int cs = tid & 7;                   // cols cs*4 .. +3
    const int ub = ks << 3;
    const int w  = tid >> 5;
    const int l  = tid & 31;

    const int gate = tid >> 7;                // tid<256: 0=z, 1=r
    const int rb   = (tid >> 5) & 3;
    const int rc   = tid & 31;

    // ---- weights: Wh -> SMEM, Wz/Wr -> registers ----
    for (int i = tid; i < (512 * 32) / 4; i += 512) {
        int f = i << 2;
        int u = f >> 5, c = f & 31;
        *(float4*)&s->wh[f] = *(const float4*)&RK[(size_t)u * 1536 + 1024 + j0 + c];
    }
    float4 wz[8], wr[8];
#pragma unroll
    for (int uu = 0; uu < 8; uu++) {
        const float* bp = &RK[(size_t)(ub + uu) * 1536 + j0 + (cs << 2)];
        wz[uu] = *(const float4*)bp;
        wr[uu] = *(const float4*)(bp + 512);
    }

    if (tid == 0) s->c0 = *(volatile unsigned*)&g_cnt[grp];
    __syncthreads();
    unsigned tcnt = s->c0;                    // absolute count target base

    auto ARRIVE = [&]() {
        __syncthreads();                      // CTA-level release/acquire
        if (tid == 0) {
            __threadfence();                  // leader carries gpu-scope drain
            atomicAdd(&g_cnt[grp], 1u);
        }
    };
    auto WAIT = [&](unsigned target) {        // target = absolute count
        if (tid == 0) {
            if ((int)(*(volatile unsigned*)&g_cnt[grp] - target) < 0) {
                do {
                    __nanosleep(32);
                } while ((int)(*(volatile unsigned*)&g_cnt[grp] - target) < 0);
            }
        }
        __syncthreads();
    };

    // ---- t = 0 : h_prev = 0 ----
    float h0v = 0.0f;
    if (tid < 128) {
        size_t mrow = (size_t)(gb0 + rb) * TT * 1536;
        float z  = hsig(g_mx[mrow + j0 + rc]);
        float hh = tanhf(g_mx[mrow + 1024 + j0 + rc]);
        h0v = (1.0f - z) * hh;
        g_h[0][gb0 + rb][j0 + rc] = h0v;
    }
    ARRIVE(); tcnt += 16;
    if (tid < 128)
        out[(size_t)(gb0 + rb) * TT * UU + j0 + rc] = h0v;

#pragma unroll 1
    for (int t = 1; t < TT; t++) {
        const int bh = (t - 1) & 1;           // h buffer to read
        const int bw = t & 1;                 // h buffer to write

        // prefetch mx gate terms (independent of sync)
        float pm1 = 0.0f, pm2 = 0.0f;
        if (tid < 256) {
            size_t mrow = ((size_t)(gb0 + rb) * TT + t) * 1536;
            pm1 = __ldcg(&g_mx[mrow + (gate << 9) + j0 + rc]);
            if (tid < 128) pm2 = __ldcg(&g_mx[mrow + 1024 + j0 + rc]);
        }

        // ---- wait h(t-1) ----
        WAIT(tcnt);

        // ---- stage h(t-1) from hot buffer ----
        {
            int b = tid >> 7, ug = tid & 127;
            float4 v = __ldcg((const float4*)&g_h[bh][gb0 + b][0] + ug);
            *(float4*)&s->stage[b][ug << 2] = v;
        }
        __syncthreads();

        // ---- r pass (critical path) ----
        {
            float a[4][4];
#pragma unroll
            for (int b = 0; b < 4; b++)
#pragma unroll
                for (int c = 0; c < 4; c++) a[b][c] = 0.0f;
#pragma unroll
            for (int uu = 0; uu < 8; uu++) {
                int u = ub + uu;
                float4 wv = wr[uu];
                float h0 = s->stage[0][u], h1 = s->stage[1][u];
                float h2 = s->stage[2][u], h3 = s->stage[3][u];
                a[0][0] = fmaf(h0, wv.x, a[0][0]); a[0][1] = fmaf(h0, wv.y, a[0][1]);
                a[0][2] = fmaf(h0, wv.z, a[0][2]); a[0][3] = fmaf(h0, wv.w, a[0][3]);
                a[1][0] = fmaf(h1, wv.x, a[1][0]); a[1][1] = fmaf(h1, wv.y, a[1][1]);
                a[1][2] = fmaf(h1, wv.z, a[1][2]); a[1][3] = fmaf(h1, wv.w, a[1][3]);
                a[2][0] = fmaf(h2, wv.x, a[2][0]); a[2][1] = fmaf(h2, wv.y, a[2][1]);
                a[2][2] = fmaf(h2, wv.z, a[2][2]); a[2][3] = fmaf(h2, wv.w, a[2][3]);
                a[3][0] = fmaf(h3, wv.x, a[3][0]); a[3][1] = fmaf(h3, wv.y, a[3][1]);
                a[3][2] = fmaf(h3, wv.z, a[3][2]); a[3][3] = fmaf(h3, wv.w, a[3][3]);
            }
#pragma unroll
            for (int b = 0; b < 4; b++)
#pragma unroll
                for (int c = 0; c < 4; c++) RED2(a[b][c]);
            if (l < 8)
#pragma unroll
                for (int b = 0; b < 4; b++)
                    *(float4*)&s->red[(w << 7) + (b << 5) + (l << 2)] =
                        make_float4(a[b][0], a[b][1], a[b][2], a[b][3]);
        }
        __syncthreads();

        // ---- r reduce -> publish rh (threads 128..255 hold pm1 = mx_r) ----
        if (gate == 1 && tid < 256) {
            int idx = tid - 128;
            float sum = pm1;
#pragma unroll
            for (int k = 0; k < 16; k++) sum += s->red[(k << 7) + idx];
            float r = hsig(sum);
            g_rh[(size_t)(gb0 + rb) * UU + j0 + rc] = r * s->stage[rb][j0 + rc];
        }
        ARRIVE(); tcnt += 16;     // rh published  (no wait yet)

        // ======== hidden work: z pass while peers publish rh ========
        {
            float a[4][4];
#pragma unroll
            for (int b = 0; b < 4; b++)
#pragma unroll
                for (int c = 0; c < 4; c++) a[b][c] = 0.0f;
#pragma unroll
            for (int uu = 0; uu < 8; uu++) {
                int u = ub + uu;
                float4 wv = wz[uu];
                float h0 = s->stage[0][u], h1 = s->stage[1][u];
                float h2 = s->stage[2][u], h3 = s->stage[3][u];
                a[0][0] = fmaf(h0, wv.x, a[0][0]); a[0][1] = fmaf(h0, wv.y, a[0][1]);
                a[0][2] = fmaf(h0, wv.z, a[0][2]); a[0][3] = fmaf(h0, wv.w, a[0][3]);
                a[1][0] = fmaf(h1, wv.x, a[1][0]); a[1][1] = fmaf(h1, wv.y, a[1][1]);
                a[1][2] = fmaf(h1, wv.z, a[1][2]); a[1][3] = fmaf(h1, wv.w, a[1][3]);
                a[2][0] = fmaf(h2, wv.x, a[2][0]); a[2][1] = fmaf(h2, wv.y, a[2][1]);
                a[2][2] = fmaf(h2, wv.z, a[2][2]); a[2][3] = fmaf(h2, wv.w, a[2][3]);
                a[3][0] = fmaf(h3, wv.x, a[3][0]); a[3][1] = fmaf(h3, wv.y, a[3][1]);
                a[3][2] = fmaf(h3, wv.z, a[3][2]); a[3][3] = fmaf(h3, wv.w, a[3][3]);
            }
#pragma unroll
            for (int b = 0; b < 4; b++)
#pragma unroll
                for (int c = 0; c < 4; c++) RED2(a[b][c]);
            if (l < 8)
#pragma unroll
                for (int b = 0; b < 4; b++)
                    *(float4*)&s->red[(w << 7) + (b << 5) + (l << 2)] =
                        make_float4(a[b][0], a[b][1], a[b][2], a[b][3]);
        }
        __syncthreads();
        if (gate == 0 && tid < 128) {     // threads 0..127 hold pm1 = mx_z
            float sum = pm1;
#pragma unroll
            for (int k = 0; k < 16; k++) sum += s->red[(k << 7) + tid];
            s->zs[tid]   = hsig(sum);
            s->hown[tid] = s->stage[rb][j0 + rc];
        }
        // ============================================================

        // ---- wait rh from all group CTAs, stage it ----
        WAIT(tcnt);
        {
            int b = tid >> 7, ug = tid & 127;
            float4 v = __ldcg((const float4*)(g_rh + (size_t)(gb0 + b) * UU) + ug);
            *(float4*)&s->stage[b][ug << 2] = v;
        }
        __syncthreads();

        // ---- h-candidate pass (Wh from SMEM) ----
        {
            float a[4][4];
#pragma unroll
            for (int b = 0; b < 4; b++)
#pragma unroll
                for (int c = 0; c < 4; c++) a[b][c] = 0.0f;
#pragma unroll
            for (int uu = 0; uu < 8; uu++) {
                int u = ub + uu;
                float4 wv = *(const float4*)&s->wh[(u << 5) + (cs << 2)];
                float h0 = s->stage[0][u], h1 = s->stage[1][u];
                float h2 = s->stage[2][u], h3 = s->stage[3][u];
                a[0][0] = fmaf(h0, wv.x, a[0][0]); a[0][1] = fmaf(h0, wv.y, a[0][1]);
                a[0][2] = fmaf(h0, wv.z, a[0][2]); a[0][3] = fmaf(h0, wv.w, a[0][3]);
                a[1][0] = fmaf(h1, wv.x, a[1][0]); a[1][1] = fmaf(h1, wv.y, a[1][1]);
                a[1][2] = fmaf(h1, wv.z, a[1][2]); a[1][3] = fmaf(h1, wv.w, a[1][3]);
                a[2][0] = fmaf(h2, wv.x, a[2][0]); a[2][1] = fmaf(h2, wv.y, a[2][1]);
                a[2][2] = fmaf(h2, wv.z, a[2][2]); a[2][3] = fmaf(h2, wv.w, a[2][3]);
                a[3][0] = fmaf(h3, wv.x, a[3][0]); a[3][1] = fmaf(h3, wv.y, a[3][1]);
                a[3][2] = fmaf(h3, wv.z, a[3][2]); a[3][3] = fmaf(h3, wv.w, a[3][3]);
            }
#pragma unroll
            for (int b = 0; b < 4; b++)
#pragma unroll
                for (int c = 0; c < 4; c++) RED2(a[b][c]);
            if (l < 8)
#pragma unroll
                for (int b = 0; b < 4; b++)
                    *(float4*)&s->red[(w << 7) + (b << 5) + (l << 2)] =
                        make_float4(a[b][0], a[b][1], a[b][2], a[b][3]);
        }
        __syncthreads();

        // ---- final: h(t) -> hot buffer, then publish ----
        float hn = 0.0f;
        if (tid < 128) {
            float sum = pm2;
#pragma unroll
            for (int k = 0; k < 16; k++) sum += s->red[(k << 7) + tid];
            float hh = tanhf(sum);
            float z  = s->zs[tid];
            float hp = s->hown[tid];
            hn = z * hp + (1.0f - z) * hh;
            g_h[bw][gb0 + rb][j0 + rc] = hn;
        }
        ARRIVE(); tcnt += 16;     // h(t) published; wait at next loop top

        // lazy output write (off critical path, outside fence set)
        if (tid < 128)
            out[((size_t)(gb0 + rb) * TT + t) * UU + j0 + rc] = hn;
    }
}

// ---------------------------------------------------------------------------
extern "C" void kernel_launch(void* const* d_in, const int* in_sizes, int n_in,
                              void* d_out, int out_size) {
    const float* x    = (const float*)d_in[0];
    const float* ker  = (const float*)d_in[1];
    const float* rk   = (const float*)d_in[2];
    const float* bias = (const float*)d_in[3];
    float* out = (float*)d_out;
    (void)in_sizes; (void)n_in; (void)out_size;

    static bool attr_set = false;
    if (!attr_set) {
        cudaFuncSetAttribute(gru16, cudaFuncAttributeMaxDynamicSharedMemorySize,
                             SM16_BYTES);
        attr_set = true;
    }

    dim3 gg(24, 128);
    mx_gemm<<<gg, 256>>>(x, ker, bias);
    gru16<<<128, 512, SM16_BYTES>>>(rk, out);
}